// round 1
// baseline (speedup 1.0000x reference)
#include <cuda_runtime.h>
#include <math.h>

#define S_LEN 2048
#define HID   4096
#define NH    32
#define NKV   8
#define HD    128

// ---------------- device scratch (no allocs allowed) ----------------
__device__ float    g_q[S_LEN * NH * HD];     // 32 MB
__device__ float    g_k[S_LEN * NKV * HD];    // 8 MB
__device__ float    g_v[S_LEN * NKV * HD];    // 8 MB
__device__ float    g_attn[S_LEN * NH * HD];  // 32 MB
__device__ unsigned g_amax[3];                // absmax bits for q,k,v

// ---------------- reset reducers (must run every replay) ----------------
__global__ void reset_amax_kernel()
{
    if (threadIdx.x < 3) g_amax[threadIdx.x] = 0u;
}

// ---------------- fp32 SGEMM: C[M,N] = A[M,K] @ B[K,N], all row-major ----------------
// BM=BN=128, BK=16, 256 threads, 8x8 micro-tile. M%128==0, N%128==0, K%16==0 assumed.
__global__ __launch_bounds__(256) void sgemm128(const float* __restrict__ A,
                                                const float* __restrict__ B,
                                                float* __restrict__ C,
                                                int M, int N, int K)
{
    __shared__ float As[16][132];   // transposed A tile, padded vs bank conflicts
    __shared__ float Bs[16][128];

    const int t  = threadIdx.x;
    const int tx = t & 15;
    const int ty = t >> 4;
    const int row0 = blockIdx.y * 128;
    const int col0 = blockIdx.x * 128;

    float acc[8][8];
#pragma unroll
    for (int i = 0; i < 8; i++)
#pragma unroll
        for (int j = 0; j < 8; j++) acc[i][j] = 0.f;

    const float* Ab = A + (size_t)row0 * K;
    const float* Bb = B + col0;

    for (int kt = 0; kt < K; kt += 16) {
#pragma unroll
        for (int i = 0; i < 2; i++) {
            int u = t + i * 256;              // 512 float4 units of the 128x16 A tile
            int r = u >> 2, c4 = u & 3;
            float4 va = *(const float4*)(Ab + (size_t)r * K + kt + c4 * 4);
            As[c4 * 4 + 0][r] = va.x;
            As[c4 * 4 + 1][r] = va.y;
            As[c4 * 4 + 2][r] = va.z;
            As[c4 * 4 + 3][r] = va.w;
        }
#pragma unroll
        for (int i = 0; i < 2; i++) {
            int u = t + i * 256;              // 512 float4 units of the 16x128 B tile
            int r = u >> 5, c4 = u & 31;
            *((float4*)&Bs[r][0] + c4) = *(const float4*)(Bb + (size_t)(kt + r) * N + c4 * 4);
        }
        __syncthreads();
#pragma unroll
        for (int k = 0; k < 16; k++) {
            float a[8], b[8];
            *(float4*)&a[0] = *(const float4*)&As[k][ty * 8];
            *(float4*)&a[4] = *(const float4*)&As[k][ty * 8 + 4];
            *(float4*)&b[0] = *(const float4*)&Bs[k][tx * 8];
            *(float4*)&b[4] = *(const float4*)&Bs[k][tx * 8 + 4];
#pragma unroll
            for (int i = 0; i < 8; i++)
#pragma unroll
                for (int j = 0; j < 8; j++)
                    acc[i][j] = fmaf(a[i], b[j], acc[i][j]);
        }
        __syncthreads();
    }
#pragma unroll
    for (int i = 0; i < 8; i++) {
        float* Cp = C + (size_t)(row0 + ty * 8 + i) * N + col0 + tx * 8;
        *(float4*)Cp       = make_float4(acc[i][0], acc[i][1], acc[i][2], acc[i][3]);
        *(float4*)(Cp + 4) = make_float4(acc[i][4], acc[i][5], acc[i][6], acc[i][7]);
    }
}

// ---------------- RoPE (in place) + global absmax ----------------
__global__ __launch_bounds__(256) void rope_absmax_kernel(float* __restrict__ buf, int nheads,
                                                          const int* __restrict__ pos_ids, int slot)
{
    int idx = blockIdx.x * 256 + threadIdx.x;
    int total = S_LEN * nheads * 64;
    float local = 0.f;
    if (idx < total) {
        int i = idx & 63;
        int h = (idx >> 6) % nheads;
        int s = idx / (64 * nheads);
        size_t base = (size_t)s * nheads * HD + (size_t)h * HD;
        float x1 = buf[base + i];
        float x2 = buf[base + 64 + i];
        // inv_freq = 10000^(-i/64); ln(10000) = 9.210340371976184
        float invf = expf(-(float)i * (1.0f / 64.0f) * 9.210340371976184f);
        float ang = (float)pos_ids[s] * invf;
        float c, sn;
        sincosf(ang, &sn, &c);
        float o1 = x1 * c - x2 * sn;
        float o2 = x2 * c + x1 * sn;
        buf[base + i]      = o1;
        buf[base + 64 + i] = o2;
        local = fmaxf(fabsf(o1), fabsf(o2));
    }
    // block-reduce max (float bits: monotone for non-negative floats)
    unsigned bits = __float_as_uint(local);
#pragma unroll
    for (int o = 16; o; o >>= 1) bits = max(bits, __shfl_xor_sync(0xffffffffu, bits, o));
    __shared__ unsigned sred[8];
    int wid = threadIdx.x >> 5;
    if ((threadIdx.x & 31) == 0) sred[wid] = bits;
    __syncthreads();
    if (threadIdx.x == 0) {
        unsigned m = sred[0];
#pragma unroll
        for (int w = 1; w < 8; w++) m = max(m, sred[w]);
        atomicMax(&g_amax[slot], m);
    }
}

__global__ __launch_bounds__(256) void absmax_kernel(const float* __restrict__ buf, int n, int slot)
{
    int idx = blockIdx.x * 256 + threadIdx.x;
    float local = (idx < n) ? fabsf(buf[idx]) : 0.f;
    unsigned bits = __float_as_uint(local);
#pragma unroll
    for (int o = 16; o; o >>= 1) bits = max(bits, __shfl_xor_sync(0xffffffffu, bits, o));
    __shared__ unsigned sred[8];
    int wid = threadIdx.x >> 5;
    if ((threadIdx.x & 31) == 0) sred[wid] = bits;
    __syncthreads();
    if (threadIdx.x == 0) {
        unsigned m = sred[0];
#pragma unroll
        for (int w = 1; w < 8; w++) m = max(m, sred[w]);
        atomicMax(&g_amax[slot], m);
    }
}

// ---------------- fake quant in place: x = rint(x/scale)*scale, scale = max/127 ----------------
__global__ __launch_bounds__(256) void quant_kernel(float* __restrict__ buf, int n, int slot)
{
    int idx = blockIdx.x * 256 + threadIdx.x;
    if (idx < n) {
        float mx = __uint_as_float(g_amax[slot]);
        float sc = mx / 127.0f;          // matches jnp: max/QMAX
        float x  = buf[idx];
        buf[idx] = rintf(x / sc) * sc;   // rintf = round half-to-even = jnp.round
    }
}

// ---------------- flash attention, fp32, causal, GQA ----------------
#define FBM 64
#define FBN 64
#define KST 132   // K/V tile row stride (pad: 2-way instead of 16-way conflicts)
#define SST 68    // score tile row stride (conflict-free softmax + aligned float4)
#define FLASH_SMEM ((FBM * HD + FBN * KST + FBM * SST + 3 * FBM) * 4)

__global__ __launch_bounds__(256) void flash_kernel(const float* __restrict__ Q,
                                                    const float* __restrict__ Kb,
                                                    const float* __restrict__ Vb,
                                                    float* __restrict__ O)
{
    extern __shared__ float sm[];
    float* Qs   = sm;                    // FBM x HD
    float* KVs  = Qs + FBM * HD;         // FBN x KST (K tile, then reused for V tile)
    float* Ss   = KVs + FBN * KST;       // FBM x SST
    float* m_s  = Ss + FBM * SST;
    float* l_s  = m_s + FBM;
    float* al_s = l_s + FBM;

    const int qt  = (int)gridDim.x - 1 - (int)blockIdx.x;  // heavy tiles scheduled first
    const int h   = blockIdx.y;
    const int kvh = h >> 2;                                // N_GROUPS = 4
    const int t   = threadIdx.x;
    const int tx  = t & 15, ty = t >> 4;
    const int q0  = qt * FBM;

    // load Q tile (64 x 128)
#pragma unroll
    for (int i = 0; i < 8; i++) {
        int u = t + i * 256;
        int r = u >> 5, c4 = u & 31;
        *((float4*)(Qs + r * HD) + c4) =
            *(const float4*)(Q + (size_t)(q0 + r) * (NH * HD) + (size_t)h * HD + c4 * 4);
    }
    if (t < FBM) { m_s[t] = -INFINITY; l_s[t] = 0.f; }

    float acc[4][8];
#pragma unroll
    for (int i = 0; i < 4; i++)
#pragma unroll
        for (int j = 0; j < 8; j++) acc[i][j] = 0.f;

    const int sr0 = ty * 4;   // S / O rows owned by this thread
    const int sc0 = tx * 4;   // S cols
    const int oc0 = tx * 8;   // O cols
    const int row = t >> 2, lane = t & 3;
    const float scale = 0.08838834764831845f;  // 1/sqrt(128)

    for (int j = 0; j <= qt; j++) {
        int k0 = j * FBN;
        __syncthreads();   // prior PV reads of KVs done
        // K tile
#pragma unroll
        for (int i = 0; i < 8; i++) {
            int u = t + i * 256;
            int r = u >> 5, c4 = u & 31;
            *((float4*)(KVs + r * KST) + c4) =
                *(const float4*)(Kb + (size_t)(k0 + r) * (NKV * HD) + (size_t)kvh * HD + c4 * 4);
        }
        __syncthreads();

        // S = Q K^T  (4x4 micro-tile per thread)
        float sacc[4][4] = {};
#pragma unroll 8
        for (int d4 = 0; d4 < 32; d4++) {
            float4 qv[4], kv[4];
#pragma unroll
            for (int i = 0; i < 4; i++) qv[i] = *((const float4*)(Qs + (sr0 + i) * HD) + d4);
#pragma unroll
            for (int i = 0; i < 4; i++) kv[i] = *((const float4*)(KVs + (sc0 + i) * KST) + d4);
#pragma unroll
            for (int i = 0; i < 4; i++)
#pragma unroll
                for (int jj = 0; jj < 4; jj++) {
                    sacc[i][jj] = fmaf(qv[i].x, kv[jj].x, sacc[i][jj]);
                    sacc[i][jj] = fmaf(qv[i].y, kv[jj].y, sacc[i][jj]);
                    sacc[i][jj] = fmaf(qv[i].z, kv[jj].z, sacc[i][jj]);
                    sacc[i][jj] = fmaf(qv[i].w, kv[jj].w, sacc[i][jj]);
                }
        }
        // scale + causal mask -> Ss
#pragma unroll
        for (int i = 0; i < 4; i++) {
            int gq = q0 + sr0 + i;
            float4 sv;
            sv.x = sacc[i][0] * scale + ((k0 + sc0 + 0) > gq ? -1e9f : 0.f);
            sv.y = sacc[i][1] * scale + ((k0 + sc0 + 1) > gq ? -1e9f : 0.f);
            sv.z = sacc[i][2] * scale + ((k0 + sc0 + 2) > gq ? -1e9f : 0.f);
            sv.w = sacc[i][3] * scale + ((k0 + sc0 + 3) > gq ? -1e9f : 0.f);
            *((float4*)(Ss + (sr0 + i) * SST + sc0)) = sv;
        }
        __syncthreads();

        // online softmax: 4 threads (quad) per row
        {
            float* srow = Ss + row * SST;
            float mloc = -INFINITY;
#pragma unroll
            for (int jj = 0; jj < 16; jj++) mloc = fmaxf(mloc, srow[lane + jj * 4]);
            mloc = fmaxf(mloc, __shfl_xor_sync(0xffffffffu, mloc, 1));
            mloc = fmaxf(mloc, __shfl_xor_sync(0xffffffffu, mloc, 2));
            float mold = m_s[row];
            float mnew = fmaxf(mold, mloc);
            float alpha = expf(mold - mnew);
            float ssum = 0.f;
#pragma unroll
            for (int jj = 0; jj < 16; jj++) {
                float p = expf(srow[lane + jj * 4] - mnew);
                srow[lane + jj * 4] = p;
                ssum += p;
            }
            ssum += __shfl_xor_sync(0xffffffffu, ssum, 1);
            ssum += __shfl_xor_sync(0xffffffffu, ssum, 2);
            if (lane == 0) {
                m_s[row]  = mnew;
                l_s[row]  = l_s[row] * alpha + ssum;
                al_s[row] = alpha;
            }
        }
        // V tile into KVs (K reads finished before the previous sync)
#pragma unroll
        for (int i = 0; i < 8; i++) {
            int u = t + i * 256;
            int r = u >> 5, c4 = u & 31;
            *((float4*)(KVs + r * KST) + c4) =
                *(const float4*)(Vb + (size_t)(k0 + r) * (NKV * HD) + (size_t)kvh * HD + c4 * 4);
        }
        __syncthreads();

        // rescale running O, then O += P V
        {
            float a0 = al_s[sr0 + 0], a1 = al_s[sr0 + 1], a2 = al_s[sr0 + 2], a3 = al_s[sr0 + 3];
#pragma unroll
            for (int jj = 0; jj < 8; jj++) {
                acc[0][jj] *= a0; acc[1][jj] *= a1; acc[2][jj] *= a2; acc[3][jj] *= a3;
            }
        }
#pragma unroll 4
        for (int kk = 0; kk < FBN; kk++) {
            float p0 = Ss[(sr0 + 0) * SST + kk];
            float p1 = Ss[(sr0 + 1) * SST + kk];
            float p2 = Ss[(sr0 + 2) * SST + kk];
            float p3 = Ss[(sr0 + 3) * SST + kk];
            float4 v0 = *((const float4*)(KVs + kk * KST) + (oc0 >> 2));
            float4 v1 = *((const float4*)(KVs + kk * KST) + (oc0 >> 2) + 1);
            acc[0][0] = fmaf(p0, v0.x, acc[0][0]); acc[0][1] = fmaf(p0, v0.y, acc[0][1]);
            acc[0][2] = fmaf(p0, v0.z, acc[0][2]); acc[0][3] = fmaf(p0, v0.w, acc[0][3]);
            acc[0][4] = fmaf(p0, v1.x, acc[0][4]); acc[0][5] = fmaf(p0, v1.y, acc[0][5]);
            acc[0][6] = fmaf(p0, v1.z, acc[0][6]); acc[0][7] = fmaf(p0, v1.w, acc[0][7]);
            acc[1][0] = fmaf(p1, v0.x, acc[1][0]); acc[1][1] = fmaf(p1, v0.y, acc[1][1]);
            acc[1][2] = fmaf(p1, v0.z, acc[1][2]); acc[1][3] = fmaf(p1, v0.w, acc[1][3]);
            acc[1][4] = fmaf(p1, v1.x, acc[1][4]); acc[1][5] = fmaf(p1, v1.y, acc[1][5]);
            acc[1][6] = fmaf(p1, v1.z, acc[1][6]); acc[1][7] = fmaf(p1, v1.w, acc[1][7]);
            acc[2][0] = fmaf(p2, v0.x, acc[2][0]); acc[2][1] = fmaf(p2, v0.y, acc[2][1]);
            acc[2][2] = fmaf(p2, v0.z, acc[2][2]); acc[2][3] = fmaf(p2, v0.w, acc[2][3]);
            acc[2][4] = fmaf(p2, v1.x, acc[2][4]); acc[2][5] = fmaf(p2, v1.y, acc[2][5]);
            acc[2][6] = fmaf(p2, v1.z, acc[2][6]); acc[2][7] = fmaf(p2, v1.w, acc[2][7]);
            acc[3][0] = fmaf(p3, v0.x, acc[3][0]); acc[3][1] = fmaf(p3, v0.y, acc[3][1]);
            acc[3][2] = fmaf(p3, v0.z, acc[3][2]); acc[3][3] = fmaf(p3, v0.w, acc[3][3]);
            acc[3][4] = fmaf(p3, v1.x, acc[3][4]); acc[3][5] = fmaf(p3, v1.y, acc[3][5]);
            acc[3][6] = fmaf(p3, v1.z, acc[3][6]); acc[3][7] = fmaf(p3, v1.w, acc[3][7]);
        }
    }

    // epilogue: normalize and store
#pragma unroll
    for (int i = 0; i < 4; i++) {
        float l = l_s[sr0 + i];
        float* Op = O + (size_t)(q0 + sr0 + i) * (NH * HD) + (size_t)h * HD + oc0;
        *(float4*)Op       = make_float4(acc[i][0] / l, acc[i][1] / l, acc[i][2] / l, acc[i][3] / l);
        *(float4*)(Op + 4) = make_float4(acc[i][4] / l, acc[i][5] / l, acc[i][6] / l, acc[i][7] / l);
    }
}

// ---------------- launch ----------------
extern "C" void kernel_launch(void* const* d_in, const int* in_sizes, int n_in,
                              void* d_out, int out_size)
{
    (void)in_sizes; (void)n_in; (void)out_size;
    const float* hs  = (const float*)d_in[0];
    // d_in[1] = attention_mask: exactly causal 0/-1e9 -> computed analytically in flash_kernel
    const int*   pos = (const int*)d_in[2];
    const float* wq  = (const float*)d_in[3];
    const float* wk  = (const float*)d_in[4];
    const float* wv  = (const float*)d_in[5];
    const float* wo  = (const float*)d_in[6];
    float*       out = (float*)d_out;

    float *q, *k, *v, *attn;
    cudaGetSymbolAddress((void**)&q,    g_q);
    cudaGetSymbolAddress((void**)&k,    g_k);
    cudaGetSymbolAddress((void**)&v,    g_v);
    cudaGetSymbolAddress((void**)&attn, g_attn);

    reset_amax_kernel<<<1, 32>>>();

    // projections
    sgemm128<<<dim3(HID / 128, S_LEN / 128), 256>>>(hs, wq, q, S_LEN, NH * HD, HID);
    sgemm128<<<dim3((NKV * HD) / 128, S_LEN / 128), 256>>>(hs, wk, k, S_LEN, NKV * HD, HID);
    sgemm128<<<dim3((NKV * HD) / 128, S_LEN / 128), 256>>>(hs, wv, v, S_LEN, NKV * HD, HID);

    // rope + absmax (q,k), absmax (v)
    rope_absmax_kernel<<<(S_LEN * NH * 64) / 256, 256>>>(q, NH, pos, 0);
    rope_absmax_kernel<<<(S_LEN * NKV * 64) / 256, 256>>>(k, NKV, pos, 1);
    absmax_kernel<<<(S_LEN * NKV * HD) / 256, 256>>>(v, S_LEN * NKV * HD, 2);

    // fake quant
    quant_kernel<<<(S_LEN * NH * HD) / 256, 256>>>(q, S_LEN * NH * HD, 0);
    quant_kernel<<<(S_LEN * NKV * HD) / 256, 256>>>(k, S_LEN * NKV * HD, 1);
    quant_kernel<<<(S_LEN * NKV * HD) / 256, 256>>>(v, S_LEN * NKV * HD, 2);

    // attention
    cudaFuncSetAttribute(flash_kernel, cudaFuncAttributeMaxDynamicSharedMemorySize, FLASH_SMEM);
    flash_kernel<<<dim3(S_LEN / FBM, NH), 256, FLASH_SMEM>>>(q, k, v, attn);

    // output projection
    sgemm128<<<dim3(HID / 128, S_LEN / 128), 256>>>(attn, wo, out, S_LEN, HID, HID);
}

// round 3
// speedup vs baseline: 1.8226x; 1.8226x over previous
#include <cuda_runtime.h>
#include <cuda_bf16.h>
#include <math.h>
#include <stdint.h>

#define S_LEN 2048
#define HID   4096
#define NH    32
#define NKV   8
#define HD    128

// ---------------- device scratch (no allocs allowed) ----------------
__device__ float          g_q[S_LEN * NH * HD];      // 32 MB
__device__ float          g_k[S_LEN * NKV * HD];     // 8 MB
__device__ float          g_v[S_LEN * NKV * HD];     // 8 MB
__device__ float          g_attn[S_LEN * NH * HD];   // 32 MB
__device__ unsigned       g_amax[3];

// split-bf16 operands
__device__ __nv_bfloat16  g_hs_h[S_LEN * HID];
__device__ __nv_bfloat16  g_hs_l[S_LEN * HID];
__device__ __nv_bfloat16  g_at_h[S_LEN * NH * HD];
__device__ __nv_bfloat16  g_at_l[S_LEN * NH * HD];
__device__ __nv_bfloat16  g_wqt_h[HID * (NH * HD)];  // [N,K] transposed
__device__ __nv_bfloat16  g_wqt_l[HID * (NH * HD)];
__device__ __nv_bfloat16  g_wkt_h[(NKV * HD) * HID];
__device__ __nv_bfloat16  g_wkt_l[(NKV * HD) * HID];
__device__ __nv_bfloat16  g_wvt_h[(NKV * HD) * HID];
__device__ __nv_bfloat16  g_wvt_l[(NKV * HD) * HID];
__device__ __nv_bfloat16  g_wot_h[HID * HID];
__device__ __nv_bfloat16  g_wot_l[HID * HID];

// ---------------- helpers ----------------
__device__ __forceinline__ uint32_t smem_u32(const void* p) {
    uint32_t a;
    asm("{ .reg .u64 t; cvta.to.shared.u64 t, %1; cvt.u32.u64 %0, t; }" : "=r"(a) : "l"(p));
    return a;
}

__device__ __forceinline__ void cp_async16(uint32_t saddr, const void* gaddr) {
    asm volatile("cp.async.cg.shared.global [%0], [%1], 16;" :: "r"(saddr), "l"(gaddr));
}
__device__ __forceinline__ void cp_commit() { asm volatile("cp.async.commit_group;"); }
__device__ __forceinline__ void cp_wait0()  { asm volatile("cp.async.wait_group 0;" ::: "memory"); }
__device__ __forceinline__ void cp_wait1()  { asm volatile("cp.async.wait_group 1;" ::: "memory"); }

__device__ __forceinline__ void ldsm_x4(uint32_t* r, uint32_t addr) {
    asm volatile("ldmatrix.sync.aligned.m8n8.x4.shared.b16 {%0,%1,%2,%3}, [%4];"
                 : "=r"(r[0]), "=r"(r[1]), "=r"(r[2]), "=r"(r[3]) : "r"(addr));
}

__device__ __forceinline__ void mma16816(float* d, const uint32_t* a, const uint32_t* b) {
    asm volatile("mma.sync.aligned.m16n8k16.row.col.f32.bf16.bf16.f32 "
                 "{%0,%1,%2,%3}, {%4,%5,%6,%7}, {%8,%9}, {%0,%1,%2,%3};"
                 : "+f"(d[0]), "+f"(d[1]), "+f"(d[2]), "+f"(d[3])
                 : "r"(a[0]), "r"(a[1]), "r"(a[2]), "r"(a[3]), "r"(b[0]), "r"(b[1]));
}

// ---------------- reset reducers ----------------
__global__ void reset_amax_kernel()
{
    if (threadIdx.x < 3) g_amax[threadIdx.x] = 0u;
}

// ---------------- fp32 -> split bf16 (elementwise) ----------------
__global__ __launch_bounds__(256) void split_kernel(const float* __restrict__ X,
                                                    __nv_bfloat16* __restrict__ H,
                                                    __nv_bfloat16* __restrict__ L, int n)
{
    int i = blockIdx.x * 256 + threadIdx.x;
    if (i < n) {
        float x = X[i];
        __nv_bfloat16 h = __float2bfloat16(x);
        H[i] = h;
        L[i] = __float2bfloat16(x - __bfloat162float(h));
    }
}

// ---------------- W[K,N] fp32 -> Wt[N,K] split bf16 ----------------
__global__ __launch_bounds__(256) void transpose_split_kernel(const float* __restrict__ W,
                                                              __nv_bfloat16* __restrict__ Th,
                                                              __nv_bfloat16* __restrict__ Tl,
                                                              int K, int N)
{
    __shared__ float s[32][33];
    int k0 = blockIdx.y * 32, n0 = blockIdx.x * 32;
    int tx = threadIdx.x & 31, ty = threadIdx.x >> 5;
#pragma unroll
    for (int i = 0; i < 32; i += 8)
        s[ty + i][tx] = W[(size_t)(k0 + ty + i) * N + n0 + tx];
    __syncthreads();
#pragma unroll
    for (int i = 0; i < 32; i += 8) {
        float x = s[tx][ty + i];
        __nv_bfloat16 h = __float2bfloat16(x);
        Th[(size_t)(n0 + ty + i) * K + k0 + tx] = h;
        Tl[(size_t)(n0 + ty + i) * K + k0 + tx] = __float2bfloat16(x - __bfloat162float(h));
    }
}

// ---------------- split-bf16 tensor-core GEMM: C[M,N] = A[M,K] @ B^T, B stored [N,K] ----
// 128x128 CTA tile, BK=64, 8 warps (64x32 warp tile), cp.async double-buffered,
// XOR-swizzled smem, mma.sync m16n8k16 bf16, 3-term split (AhBh + AhBl + AlBh).
#define MM_SMEM (2 * 65536)

// tile byte offset with XOR swizzle: 128B rows, 16B units, unit ^= row&7
__device__ __forceinline__ uint32_t tswz(int row, int cb) {
    return (uint32_t)(row * 128 + ((cb ^ (row & 7)) << 4));
}

__global__ __launch_bounds__(256) void mm_bf16x3(const __nv_bfloat16* __restrict__ Ah,
                                                 const __nv_bfloat16* __restrict__ Al,
                                                 const __nv_bfloat16* __restrict__ Bh,
                                                 const __nv_bfloat16* __restrict__ Bl,
                                                 float* __restrict__ C,
                                                 int M, int N, int K)
{
    extern __shared__ char smem[];
    const uint32_t sb = smem_u32(smem);

    const int t    = threadIdx.x;
    const int wid  = t >> 5;
    const int lane = t & 31;
    const int m0   = blockIdx.y * 128;
    const int n0   = blockIdx.x * 128;
    const int wm0  = (wid >> 2) * 64;   // warp row offset in CTA tile
    const int wn0  = (wid & 3) * 32;    // warp col offset

    const __nv_bfloat16* gbuf[4] = {
        Ah + (size_t)m0 * K, Al + (size_t)m0 * K,
        Bh + (size_t)n0 * K, Bl + (size_t)n0 * K };

    // per-thread load slots: 4 uint4 per buffer per chunk
    const int lrow = t >> 3;        // 0..31 base row (x4 via +32 steps)
    const int lcb  = t & 7;         // 16B unit

    float acc[4][4][4];
#pragma unroll
    for (int i = 0; i < 4; i++)
#pragma unroll
        for (int j = 0; j < 4; j++)
#pragma unroll
            for (int q = 0; q < 4; q++) acc[i][j][q] = 0.f;

    const int NC = K >> 6;

    // ---- load chunk c into stage s ----
    auto load_chunk = [&](int c, int s) {
        const int k0 = c << 6;
        uint32_t stb = sb + s * 65536;
#pragma unroll
        for (int b = 0; b < 4; b++) {
            const __nv_bfloat16* g = gbuf[b] + (size_t)lrow * K + k0 + lcb * 8;
            uint32_t sm = stb + b * 16384;
#pragma unroll
            for (int i = 0; i < 4; i++) {
                cp_async16(sm + tswz(lrow + i * 32, lcb), g + (size_t)(i * 32) * K);
            }
        }
    };

    load_chunk(0, 0);
    cp_commit();

    for (int c = 0; c < NC; c++) {
        if (c + 1 < NC) { load_chunk(c + 1, (c + 1) & 1); cp_commit(); cp_wait1(); }
        else           { cp_wait0(); }
        __syncthreads();

        const uint32_t stb = sb + (c & 1) * 65536;
#pragma unroll
        for (int ks = 0; ks < 4; ks++) {
            uint32_t ahf[4][4], alf[4][4], bhf[4][2], blf[4][2];
            // A fragments (16x16 atoms): lanes 0-15 rows, lane>>4 selects k-half
            {
                const int ar = (lane & 15);
                const int acb = ks * 2 + (lane >> 4);
#pragma unroll
                for (int ma = 0; ma < 4; ma++) {
                    uint32_t ad = stb + tswz(wm0 + ma * 16 + ar, acb);
                    ldsm_x4(ahf[ma], ad);
                    ldsm_x4(alf[ma], ad + 16384);
                }
            }
            // B fragments: ldmatrix.x4 covers 2 n-atoms (klo,khi each)
            {
                const int natom = lane >> 4;          // 0/1 within pair
                const int br    = lane & 7;
                const int bcb   = ks * 2 + ((lane >> 3) & 1);
#pragma unroll
                for (int nb = 0; nb < 2; nb++) {
                    int row = wn0 + (nb * 2 + natom) * 8 + br;
                    uint32_t bd = stb + 32768 + tswz(row, bcb);
                    uint32_t r[4];
                    ldsm_x4(r, bd);
                    bhf[nb * 2 + 0][0] = r[0]; bhf[nb * 2 + 0][1] = r[1];
                    bhf[nb * 2 + 1][0] = r[2]; bhf[nb * 2 + 1][1] = r[3];
                    ldsm_x4(r, bd + 16384);
                    blf[nb * 2 + 0][0] = r[0]; blf[nb * 2 + 0][1] = r[1];
                    blf[nb * 2 + 1][0] = r[2]; blf[nb * 2 + 1][1] = r[3];
                }
            }
#pragma unroll
            for (int ma = 0; ma < 4; ma++)
#pragma unroll
                for (int na = 0; na < 4; na++) {
                    mma16816(acc[ma][na], ahf[ma], bhf[na]);
                    mma16816(acc[ma][na], ahf[ma], blf[na]);
                    mma16816(acc[ma][na], alf[ma], bhf[na]);
                }
        }
        __syncthreads();
    }

    // epilogue: c fragment -> global
    const int gid = lane >> 2, qid = lane & 3;
#pragma unroll
    for (int ma = 0; ma < 4; ma++) {
#pragma unroll
        for (int na = 0; na < 4; na++) {
            int row = m0 + wm0 + ma * 16 + gid;
            int col = n0 + wn0 + na * 8 + qid * 2;
            *(float2*)(C + (size_t)row * N + col) =
                make_float2(acc[ma][na][0], acc[ma][na][1]);
            *(float2*)(C + (size_t)(row + 8) * N + col) =
                make_float2(acc[ma][na][2], acc[ma][na][3]);
        }
    }
}

// ---------------- RoPE (in place) + global absmax ----------------
__global__ __launch_bounds__(256) void rope_absmax_kernel(float* __restrict__ buf, int nheads,
                                                          const int* __restrict__ pos_ids, int slot)
{
    int idx = blockIdx.x * 256 + threadIdx.x;
    int total = S_LEN * nheads * 64;
    float local = 0.f;
    if (idx < total) {
        int i = idx & 63;
        int h = (idx >> 6) % nheads;
        int s = idx / (64 * nheads);
        size_t base = (size_t)s * nheads * HD + (size_t)h * HD;
        float x1 = buf[base + i];
        float x2 = buf[base + 64 + i];
        float invf = expf(-(float)i * (1.0f / 64.0f) * 9.210340371976184f);
        float ang = (float)pos_ids[s] * invf;
        float cs, sn;
        sincosf(ang, &sn, &cs);
        float o1 = x1 * cs - x2 * sn;
        float o2 = x2 * cs + x1 * sn;
        buf[base + i]      = o1;
        buf[base + 64 + i] = o2;
        local = fmaxf(fabsf(o1), fabsf(o2));
    }
    unsigned bits = __float_as_uint(local);
#pragma unroll
    for (int o = 16; o; o >>= 1) bits = max(bits, __shfl_xor_sync(0xffffffffu, bits, o));
    __shared__ unsigned sred[8];
    int wid = threadIdx.x >> 5;
    if ((threadIdx.x & 31) == 0) sred[wid] = bits;
    __syncthreads();
    if (threadIdx.x == 0) {
        unsigned m = sred[0];
#pragma unroll
        for (int w = 1; w < 8; w++) m = max(m, sred[w]);
        atomicMax(&g_amax[slot], m);
    }
}

__global__ __launch_bounds__(256) void absmax_kernel(const float* __restrict__ buf, int n, int slot)
{
    int idx = blockIdx.x * 256 + threadIdx.x;
    float local = (idx < n) ? fabsf(buf[idx]) : 0.f;
    unsigned bits = __float_as_uint(local);
#pragma unroll
    for (int o = 16; o; o >>= 1) bits = max(bits, __shfl_xor_sync(0xffffffffu, bits, o));
    __shared__ unsigned sred[8];
    int wid = threadIdx.x >> 5;
    if ((threadIdx.x & 31) == 0) sred[wid] = bits;
    __syncthreads();
    if (threadIdx.x == 0) {
        unsigned m = sred[0];
#pragma unroll
        for (int w = 1; w < 8; w++) m = max(m, sred[w]);
        atomicMax(&g_amax[slot], m);
    }
}

__global__ __launch_bounds__(256) void quant_kernel(float* __restrict__ buf, int n, int slot)
{
    int idx = blockIdx.x * 256 + threadIdx.x;
    if (idx < n) {
        float mx = __uint_as_float(g_amax[slot]);
        float sc = mx / 127.0f;
        float x  = buf[idx];
        buf[idx] = rintf(x / sc) * sc;
    }
}

// ---------------- flash attention, fp32, causal, GQA ----------------
#define FBM 64
#define FBN 64
#define KST 132
#define SST 68
#define FLASH_SMEM ((FBM * HD + FBN * KST + FBM * SST + 3 * FBM) * 4)

__global__ __launch_bounds__(256) void flash_kernel(const float* __restrict__ Q,
                                                    const float* __restrict__ Kb,
                                                    const float* __restrict__ Vb,
                                                    float* __restrict__ O)
{
    extern __shared__ float sm[];
    float* Qs   = sm;
    float* KVs  = Qs + FBM * HD;
    float* Ss   = KVs + FBN * KST;
    float* m_s  = Ss + FBM * SST;
    float* l_s  = m_s + FBM;
    float* al_s = l_s + FBM;

    const int qt  = (int)gridDim.x - 1 - (int)blockIdx.x;
    const int h   = blockIdx.y;
    const int kvh = h >> 2;
    const int t   = threadIdx.x;
    const int tx  = t & 15, ty = t >> 4;
    const int q0  = qt * FBM;

#pragma unroll
    for (int i = 0; i < 8; i++) {
        int u = t + i * 256;
        int r = u >> 5, c4 = u & 31;
        *((float4*)(Qs + r * HD) + c4) =
            *(const float4*)(Q + (size_t)(q0 + r) * (NH * HD) + (size_t)h * HD + c4 * 4);
    }
    if (t < FBM) { m_s[t] = -INFINITY; l_s[t] = 0.f; }

    float acc[4][8];
#pragma unroll
    for (int i = 0; i < 4; i++)
#pragma unroll
        for (int j = 0; j < 8; j++) acc[i][j] = 0.f;

    const int sr0 = ty * 4;
    const int sc0 = tx * 4;
    const int oc0 = tx * 8;
    const int row = t >> 2, lane = t & 3;
    const float scale = 0.08838834764831845f;

    for (int j = 0; j <= qt; j++) {
        int k0 = j * FBN;
        __syncthreads();
#pragma unroll
        for (int i = 0; i < 8; i++) {
            int u = t + i * 256;
            int r = u >> 5, c4 = u & 31;
            *((float4*)(KVs + r * KST) + c4) =
                *(const float4*)(Kb + (size_t)(k0 + r) * (NKV * HD) + (size_t)kvh * HD + c4 * 4);
        }
        __syncthreads();

        float sacc[4][4] = {};
#pragma unroll 8
        for (int d4 = 0; d4 < 32; d4++) {
            float4 qv[4], kv[4];
#pragma unroll
            for (int i = 0; i < 4; i++) qv[i] = *((const float4*)(Qs + (sr0 + i) * HD) + d4);
#pragma unroll
            for (int i = 0; i < 4; i++) kv[i] = *((const float4*)(KVs + (sc0 + i) * KST) + d4);
#pragma unroll
            for (int i = 0; i < 4; i++)
#pragma unroll
                for (int jj = 0; jj < 4; jj++) {
                    sacc[i][jj] = fmaf(qv[i].x, kv[jj].x, sacc[i][jj]);
                    sacc[i][jj] = fmaf(qv[i].y, kv[jj].y, sacc[i][jj]);
                    sacc[i][jj] = fmaf(qv[i].z, kv[jj].z, sacc[i][jj]);
                    sacc[i][jj] = fmaf(qv[i].w, kv[jj].w, sacc[i][jj]);
                }
        }
#pragma unroll
        for (int i = 0; i < 4; i++) {
            int gq = q0 + sr0 + i;
            float4 sv;
            sv.x = sacc[i][0] * scale + ((k0 + sc0 + 0) > gq ? -1e9f : 0.f);
            sv.y = sacc[i][1] * scale + ((k0 + sc0 + 1) > gq ? -1e9f : 0.f);
            sv.z = sacc[i][2] * scale + ((k0 + sc0 + 2) > gq ? -1e9f : 0.f);
            sv.w = sacc[i][3] * scale + ((k0 + sc0 + 3) > gq ? -1e9f : 0.f);
            *((float4*)(Ss + (sr0 + i) * SST + sc0)) = sv;
        }
        __syncthreads();

        {
            float* srow = Ss + row * SST;
            float mloc = -INFINITY;
#pragma unroll
            for (int jj = 0; jj < 16; jj++) mloc = fmaxf(mloc, srow[lane + jj * 4]);
            mloc = fmaxf(mloc, __shfl_xor_sync(0xffffffffu, mloc, 1));
            mloc = fmaxf(mloc, __shfl_xor_sync(0xffffffffu, mloc, 2));
            float mold = m_s[row];
            float mnew = fmaxf(mold, mloc);
            float alpha = expf(mold - mnew);
            float ssum = 0.f;
#pragma unroll
            for (int jj = 0; jj < 16; jj++) {
                float p = expf(srow[lane + jj * 4] - mnew);
                srow[lane + jj * 4] = p;
                ssum += p;
            }
            ssum += __shfl_xor_sync(0xffffffffu, ssum, 1);
            ssum += __shfl_xor_sync(0xffffffffu, ssum, 2);
            if (lane == 0) {
                m_s[row]  = mnew;
                l_s[row]  = l_s[row] * alpha + ssum;
                al_s[row] = alpha;
            }
        }
#pragma unroll
        for (int i = 0; i < 8; i++) {
            int u = t + i * 256;
            int r = u >> 5, c4 = u & 31;
            *((float4*)(KVs + r * KST) + c4) =
                *(const float4*)(Vb + (size_t)(k0 + r) * (NKV * HD) + (size_t)kvh * HD + c4 * 4);
        }
        __syncthreads();

        {
            float a0 = al_s[sr0 + 0], a1 = al_s[sr0 + 1], a2 = al_s[sr0 + 2], a3 = al_s[sr0 + 3];
#pragma unroll
            for (int jj = 0; jj < 8; jj++) {
                acc[0][jj] *= a0; acc[1][jj] *= a1; acc[2][jj] *= a2; acc[3][jj] *= a3;
            }
        }
#pragma unroll 4
        for (int kk = 0; kk < FBN; kk++) {
            float p0 = Ss[(sr0 + 0) * SST + kk];
            float p1 = Ss[(sr0 + 1) * SST + kk];
            float p2 = Ss[(sr0 + 2) * SST + kk];
            float p3 = Ss[(sr0 + 3) * SST + kk];
            float4 v0 = *((const float4*)(KVs + kk * KST) + (oc0 >> 2));
            float4 v1 = *((const float4*)(KVs + kk * KST) + (oc0 >> 2) + 1);
            acc[0][0] = fmaf(p0, v0.x, acc[0][0]); acc[0][1] = fmaf(p0, v0.y, acc[0][1]);
            acc[0][2] = fmaf(p0, v0.z, acc[0][2]); acc[0][3] = fmaf(p0, v0.w, acc[0][3]);
            acc[0][4] = fmaf(p0, v1.x, acc[0][4]); acc[0][5] = fmaf(p0, v1.y, acc[0][5]);
            acc[0][6] = fmaf(p0, v1.z, acc[0][6]); acc[0][7] = fmaf(p0, v1.w, acc[0][7]);
            acc[1][0] = fmaf(p1, v0.x, acc[1][0]); acc[1][1] = fmaf(p1, v0.y, acc[1][1]);
            acc[1][2] = fmaf(p1, v0.z, acc[1][2]); acc[1][3] = fmaf(p1, v0.w, acc[1][3]);
            acc[1][4] = fmaf(p1, v1.x, acc[1][4]); acc[1][5] = fmaf(p1, v1.y, acc[1][5]);
            acc[1][6] = fmaf(p1, v1.z, acc[1][6]); acc[1][7] = fmaf(p1, v1.w, acc[1][7]);
            acc[2][0] = fmaf(p2, v0.x, acc[2][0]); acc[2][1] = fmaf(p2, v0.y, acc[2][1]);
            acc[2][2] = fmaf(p2, v0.z, acc[2][2]); acc[2][3] = fmaf(p2, v0.w, acc[2][3]);
            acc[2][4] = fmaf(p2, v1.x, acc[2][4]); acc[2][5] = fmaf(p2, v1.y, acc[2][5]);
            acc[2][6] = fmaf(p2, v1.z, acc[2][6]); acc[2][7] = fmaf(p2, v1.w, acc[2][7]);
            acc[3][0] = fmaf(p3, v0.x, acc[3][0]); acc[3][1] = fmaf(p3, v0.y, acc[3][1]);
            acc[3][2] = fmaf(p3, v0.z, acc[3][2]); acc[3][3] = fmaf(p3, v0.w, acc[3][3]);
            acc[3][4] = fmaf(p3, v1.x, acc[3][4]); acc[3][5] = fmaf(p3, v1.y, acc[3][5]);
            acc[3][6] = fmaf(p3, v1.z, acc[3][6]); acc[3][7] = fmaf(p3, v1.w, acc[3][7]);
        }
    }

#pragma unroll
    for (int i = 0; i < 4; i++) {
        float l = l_s[sr0 + i];
        float* Op = O + (size_t)(q0 + sr0 + i) * (NH * HD) + (size_t)h * HD + oc0;
        *(float4*)Op       = make_float4(acc[i][0] / l, acc[i][1] / l, acc[i][2] / l, acc[i][3] / l);
        *(float4*)(Op + 4) = make_float4(acc[i][4] / l, acc[i][5] / l, acc[i][6] / l, acc[i][7] / l);
    }
}

// ---------------- launch ----------------
extern "C" void kernel_launch(void* const* d_in, const int* in_sizes, int n_in,
                              void* d_out, int out_size)
{
    (void)in_sizes; (void)n_in; (void)out_size;
    const float* hs  = (const float*)d_in[0];
    const int*   pos = (const int*)d_in[2];
    const float* wq  = (const float*)d_in[3];
    const float* wk  = (const float*)d_in[4];
    const float* wv  = (const float*)d_in[5];
    const float* wo  = (const float*)d_in[6];
    float*       out = (float*)d_out;

    float *q, *k, *v, *attn;
    __nv_bfloat16 *hsh, *hsl, *ath, *atl;
    __nv_bfloat16 *wqh, *wql, *wkh, *wkl, *wvh, *wvl, *woh, *wol;
    cudaGetSymbolAddress((void**)&q,    g_q);
    cudaGetSymbolAddress((void**)&k,    g_k);
    cudaGetSymbolAddress((void**)&v,    g_v);
    cudaGetSymbolAddress((void**)&attn, g_attn);
    cudaGetSymbolAddress((void**)&hsh,  g_hs_h);
    cudaGetSymbolAddress((void**)&hsl,  g_hs_l);
    cudaGetSymbolAddress((void**)&ath,  g_at_h);
    cudaGetSymbolAddress((void**)&atl,  g_at_l);
    cudaGetSymbolAddress((void**)&wqh,  g_wqt_h);
    cudaGetSymbolAddress((void**)&wql,  g_wqt_l);
    cudaGetSymbolAddress((void**)&wkh,  g_wkt_h);
    cudaGetSymbolAddress((void**)&wkl,  g_wkt_l);
    cudaGetSymbolAddress((void**)&wvh,  g_wvt_h);
    cudaGetSymbolAddress((void**)&wvl,  g_wvt_l);
    cudaGetSymbolAddress((void**)&woh,  g_wot_h);
    cudaGetSymbolAddress((void**)&wol,  g_wot_l);

    cudaFuncSetAttribute(mm_bf16x3, cudaFuncAttributeMaxDynamicSharedMemorySize, MM_SMEM);
    cudaFuncSetAttribute(flash_kernel, cudaFuncAttributeMaxDynamicSharedMemorySize, FLASH_SMEM);

    reset_amax_kernel<<<1, 32>>>();

    // preprocess: split A, transpose+split weights
    split_kernel<<<(S_LEN * HID) / 256, 256>>>(hs, hsh, hsl, S_LEN * HID);
    transpose_split_kernel<<<dim3((NH * HD) / 32, HID / 32), 256>>>(wq, wqh, wql, HID, NH * HD);
    transpose_split_kernel<<<dim3((NKV * HD) / 32, HID / 32), 256>>>(wk, wkh, wkl, HID, NKV * HD);
    transpose_split_kernel<<<dim3((NKV * HD) / 32, HID / 32), 256>>>(wv, wvh, wvl, HID, NKV * HD);
    transpose_split_kernel<<<dim3(HID / 32, HID / 32), 256>>>(wo, woh, wol, NH * HD, HID);

    // projections (tensor cores)
    mm_bf16x3<<<dim3((NH * HD) / 128, S_LEN / 128), 256, MM_SMEM>>>(hsh, hsl, wqh, wql, q, S_LEN, NH * HD, HID);
    mm_bf16x3<<<dim3((NKV * HD) / 128, S_LEN / 128), 256, MM_SMEM>>>(hsh, hsl, wkh, wkl, k, S_LEN, NKV * HD, HID);
    mm_bf16x3<<<dim3((NKV * HD) / 128, S_LEN / 128), 256, MM_SMEM>>>(hsh, hsl, wvh, wvl, v, S_LEN, NKV * HD, HID);

    // rope + absmax, quant
    rope_absmax_kernel<<<(S_LEN * NH * 64) / 256, 256>>>(q, NH, pos, 0);
    rope_absmax_kernel<<<(S_LEN * NKV * 64) / 256, 256>>>(k, NKV, pos, 1);
    absmax_kernel<<<(S_LEN * NKV * HD) / 256, 256>>>(v, S_LEN * NKV * HD, 2);
    quant_kernel<<<(S_LEN * NH * HD) / 256, 256>>>(q, S_LEN * NH * HD, 0);
    quant_kernel<<<(S_LEN * NKV * HD) / 256, 256>>>(k, S_LEN * NKV * HD, 1);
    quant_kernel<<<(S_LEN * NKV * HD) / 256, 256>>>(v, S_LEN * NKV * HD, 2);

    // attention
    flash_kernel<<<dim3(S_LEN / FBM, NH), 256, FLASH_SMEM>>>(q, k, v, attn);

    // output projection (tensor cores)
    split_kernel<<<(S_LEN * NH * HD) / 256, 256>>>(attn, ath, atl, S_LEN * NH * HD);
    mm_bf16x3<<<dim3(HID / 128, S_LEN / 128), 256, MM_SMEM>>>(ath, atl, woh, wol, out, S_LEN, HID, HID);
}

// round 4
// speedup vs baseline: 3.4028x; 1.8669x over previous
#include <cuda_runtime.h>
#include <cuda_bf16.h>
#include <math.h>
#include <stdint.h>

#define S_LEN 2048
#define HID   4096
#define NH    32
#define NKV   8
#define HD    128
#define NQKV  6144   // 4096 + 1024 + 1024 fused projection width

// ---------------- device scratch (no allocs allowed) ----------------
__device__ float          g_qkv[S_LEN * NQKV];       // fused projection output (50 MB)
__device__ unsigned       g_amax[3];

__device__ __nv_bfloat16  g_qi[S_LEN * NH * HD];     // quantized integers as bf16 (exact)
__device__ __nv_bfloat16  g_ki[S_LEN * NKV * HD];
__device__ __nv_bfloat16  g_vi[S_LEN * NKV * HD];

__device__ __nv_bfloat16  g_hs_h[S_LEN * HID];       // split-bf16 activations
__device__ __nv_bfloat16  g_hs_l[S_LEN * HID];
__device__ __nv_bfloat16  g_at_h[S_LEN * NH * HD];   // attn output splits (written by flash)
__device__ __nv_bfloat16  g_at_l[S_LEN * NH * HD];
__device__ __nv_bfloat16  g_wt_h[NQKV * HID];        // fused [N,K] transposed QKV weights
__device__ __nv_bfloat16  g_wt_l[NQKV * HID];
__device__ __nv_bfloat16  g_wot_h[HID * HID];
__device__ __nv_bfloat16  g_wot_l[HID * HID];

// ---------------- helpers ----------------
__device__ __forceinline__ uint32_t smem_u32(const void* p) {
    uint32_t a;
    asm("{ .reg .u64 t; cvta.to.shared.u64 t, %1; cvt.u32.u64 %0, t; }" : "=r"(a) : "l"(p));
    return a;
}
__device__ __forceinline__ void cp_async16(uint32_t saddr, const void* gaddr) {
    asm volatile("cp.async.cg.shared.global [%0], [%1], 16;" :: "r"(saddr), "l"(gaddr));
}
__device__ __forceinline__ void cp_commit() { asm volatile("cp.async.commit_group;"); }
__device__ __forceinline__ void cp_wait0()  { asm volatile("cp.async.wait_group 0;" ::: "memory"); }
__device__ __forceinline__ void cp_wait1()  { asm volatile("cp.async.wait_group 1;" ::: "memory"); }

__device__ __forceinline__ void ldsm_x4(uint32_t* r, uint32_t addr) {
    asm volatile("ldmatrix.sync.aligned.m8n8.x4.shared.b16 {%0,%1,%2,%3}, [%4];"
                 : "=r"(r[0]), "=r"(r[1]), "=r"(r[2]), "=r"(r[3]) : "r"(addr));
}
__device__ __forceinline__ void ldsm_x4_t(uint32_t* r, uint32_t addr) {
    asm volatile("ldmatrix.sync.aligned.m8n8.x4.trans.shared.b16 {%0,%1,%2,%3}, [%4];"
                 : "=r"(r[0]), "=r"(r[1]), "=r"(r[2]), "=r"(r[3]) : "r"(addr));
}
__device__ __forceinline__ void mma16816(float* d, const uint32_t* a, const uint32_t* b) {
    asm volatile("mma.sync.aligned.m16n8k16.row.col.f32.bf16.bf16.f32 "
                 "{%0,%1,%2,%3}, {%4,%5,%6,%7}, {%8,%9}, {%0,%1,%2,%3};"
                 : "+f"(d[0]), "+f"(d[1]), "+f"(d[2]), "+f"(d[3])
                 : "r"(a[0]), "r"(a[1]), "r"(a[2]), "r"(a[3]), "r"(b[0]), "r"(b[1]));
}
// pack pair (a,b) into bf16x2 hi word + residual lo word
__device__ __forceinline__ void splitpack(float a, float b, uint32_t& hi, uint32_t& lo) {
    __nv_bfloat16 ha = __float2bfloat16(a), hb = __float2bfloat16(b);
    __nv_bfloat16 la = __float2bfloat16(a - __bfloat162float(ha));
    __nv_bfloat16 lb = __float2bfloat16(b - __bfloat162float(hb));
    hi = (uint32_t)__bfloat16_as_ushort(ha) | ((uint32_t)__bfloat16_as_ushort(hb) << 16);
    lo = (uint32_t)__bfloat16_as_ushort(la) | ((uint32_t)__bfloat16_as_ushort(lb) << 16);
}

// 128B-row swizzle (GEMM tiles) and 256B-row swizzle (flash tiles)
__device__ __forceinline__ uint32_t tswz(int row, int cb) {
    return (uint32_t)(row * 128 + ((cb ^ (row & 7)) << 4));
}
__device__ __forceinline__ uint32_t swz256(int row, int u) {
    return (uint32_t)(row * 256 + ((u ^ (row & 7)) << 4));
}

#define NEG_INF __int_as_float(0xff800000)

// ---------------- reset reducers ----------------
__global__ void reset_amax_kernel()
{
    if (threadIdx.x < 3) g_amax[threadIdx.x] = 0u;
}

// ---------------- fp32 -> split bf16 (elementwise) ----------------
__global__ __launch_bounds__(256) void split_kernel(const float* __restrict__ X,
                                                    __nv_bfloat16* __restrict__ H,
                                                    __nv_bfloat16* __restrict__ L, int n)
{
    int i = blockIdx.x * 256 + threadIdx.x;
    if (i < n) {
        float x = X[i];
        __nv_bfloat16 h = __float2bfloat16(x);
        H[i] = h;
        L[i] = __float2bfloat16(x - __bfloat162float(h));
    }
}

// ---------------- W[K,N] fp32 -> Wt[rowoff+N, K] split bf16 ----------------
__global__ __launch_bounds__(256) void transpose_split_kernel(const float* __restrict__ W,
                                                              __nv_bfloat16* __restrict__ Th,
                                                              __nv_bfloat16* __restrict__ Tl,
                                                              int K, int N, int rowoff)
{
    __shared__ float s[32][33];
    int k0 = blockIdx.y * 32, n0 = blockIdx.x * 32;
    int tx = threadIdx.x & 31, ty = threadIdx.x >> 5;
#pragma unroll
    for (int i = 0; i < 32; i += 8)
        s[ty + i][tx] = W[(size_t)(k0 + ty + i) * N + n0 + tx];
    __syncthreads();
#pragma unroll
    for (int i = 0; i < 32; i += 8) {
        float x = s[tx][ty + i];
        __nv_bfloat16 h = __float2bfloat16(x);
        Th[(size_t)(rowoff + n0 + ty + i) * K + k0 + tx] = h;
        Tl[(size_t)(rowoff + n0 + ty + i) * K + k0 + tx] = __float2bfloat16(x - __bfloat162float(h));
    }
}

// ---------------- split-bf16 tensor-core GEMM: C[M,N] = A[M,K] @ B^T, B stored [N,K] ----
#define MM_SMEM (2 * 65536)

template<int FOUR>
__global__ __launch_bounds__(256) void mm_bf16(const __nv_bfloat16* __restrict__ Ah,
                                               const __nv_bfloat16* __restrict__ Al,
                                               const __nv_bfloat16* __restrict__ Bh,
                                               const __nv_bfloat16* __restrict__ Bl,
                                               float* __restrict__ C,
                                               int M, int N, int K)
{
    extern __shared__ char smem[];
    const uint32_t sb = smem_u32(smem);

    const int t    = threadIdx.x;
    const int wid  = t >> 5;
    const int lane = t & 31;
    const int m0   = blockIdx.y * 128;
    const int n0   = blockIdx.x * 128;
    const int wm0  = (wid >> 2) * 64;
    const int wn0  = (wid & 3) * 32;

    const __nv_bfloat16* gbuf[4] = {
        Ah + (size_t)m0 * K, Al + (size_t)m0 * K,
        Bh + (size_t)n0 * K, Bl + (size_t)n0 * K };

    const int lrow = t >> 3;
    const int lcb  = t & 7;

    float acc[4][4][4];
#pragma unroll
    for (int i = 0; i < 4; i++)
#pragma unroll
        for (int j = 0; j < 4; j++)
#pragma unroll
            for (int q = 0; q < 4; q++) acc[i][j][q] = 0.f;

    const int NC = K >> 6;

    auto load_chunk = [&](int c, int s) {
        const int k0 = c << 6;
        uint32_t stb = sb + s * 65536;
#pragma unroll
        for (int b = 0; b < 4; b++) {
            const __nv_bfloat16* g = gbuf[b] + (size_t)lrow * K + k0 + lcb * 8;
            uint32_t sm = stb + b * 16384;
#pragma unroll
            for (int i = 0; i < 4; i++) {
                cp_async16(sm + tswz(lrow + i * 32, lcb), g + (size_t)(i * 32) * K);
            }
        }
    };

    load_chunk(0, 0);
    cp_commit();

    for (int c = 0; c < NC; c++) {
        if (c + 1 < NC) { load_chunk(c + 1, (c + 1) & 1); cp_commit(); cp_wait1(); }
        else           { cp_wait0(); }
        __syncthreads();

        const uint32_t stb = sb + (c & 1) * 65536;
#pragma unroll
        for (int ks = 0; ks < 4; ks++) {
            uint32_t ahf[4][4], alf[4][4], bhf[4][2], blf[4][2];
            {
                const int ar = (lane & 15);
                const int acb = ks * 2 + (lane >> 4);
#pragma unroll
                for (int ma = 0; ma < 4; ma++) {
                    uint32_t ad = stb + tswz(wm0 + ma * 16 + ar, acb);
                    ldsm_x4(ahf[ma], ad);
                    ldsm_x4(alf[ma], ad + 16384);
                }
            }
            {
                const int natom = lane >> 4;
                const int br    = lane & 7;
                const int bcb   = ks * 2 + ((lane >> 3) & 1);
#pragma unroll
                for (int nb = 0; nb < 2; nb++) {
                    int row = wn0 + (nb * 2 + natom) * 8 + br;
                    uint32_t bd = stb + 32768 + tswz(row, bcb);
                    uint32_t r[4];
                    ldsm_x4(r, bd);
                    bhf[nb * 2 + 0][0] = r[0]; bhf[nb * 2 + 0][1] = r[1];
                    bhf[nb * 2 + 1][0] = r[2]; bhf[nb * 2 + 1][1] = r[3];
                    ldsm_x4(r, bd + 16384);
                    blf[nb * 2 + 0][0] = r[0]; blf[nb * 2 + 0][1] = r[1];
                    blf[nb * 2 + 1][0] = r[2]; blf[nb * 2 + 1][1] = r[3];
                }
            }
#pragma unroll
            for (int ma = 0; ma < 4; ma++)
#pragma unroll
                for (int na = 0; na < 4; na++) {
                    mma16816(acc[ma][na], ahf[ma], bhf[na]);
                    mma16816(acc[ma][na], ahf[ma], blf[na]);
                    mma16816(acc[ma][na], alf[ma], bhf[na]);
                    if (FOUR) mma16816(acc[ma][na], alf[ma], blf[na]);
                }
        }
        __syncthreads();
    }

    const int gid = lane >> 2, qid = lane & 3;
#pragma unroll
    for (int ma = 0; ma < 4; ma++) {
#pragma unroll
        for (int na = 0; na < 4; na++) {
            int row = m0 + wm0 + ma * 16 + gid;
            int col = n0 + wn0 + na * 8 + qid * 2;
            *(float2*)(C + (size_t)row * N + col) =
                make_float2(acc[ma][na][0], acc[ma][na][1]);
            *(float2*)(C + (size_t)(row + 8) * N + col) =
                make_float2(acc[ma][na][2], acc[ma][na][3]);
        }
    }
}

// ---------------- RoPE (in place on fused buffer) + global absmax ----------------
__global__ __launch_bounds__(256) void rope_absmax_kernel(float* __restrict__ buf, int coloff,
                                                          int nheads,
                                                          const int* __restrict__ pos_ids, int slot)
{
    int idx = blockIdx.x * 256 + threadIdx.x;
    int total = S_LEN * nheads * 64;
    float local = 0.f;
    if (idx < total) {
        int i = idx & 63;
        int h = (idx >> 6) % nheads;
        int s = idx / (64 * nheads);
        size_t base = (size_t)s * NQKV + coloff + (size_t)h * HD;
        float x1 = buf[base + i];
        float x2 = buf[base + 64 + i];
        float invf = expf(-(float)i * (1.0f / 64.0f) * 9.210340371976184f);
        float ang = (float)pos_ids[s] * invf;
        float cs, sn;
        sincosf(ang, &sn, &cs);
        float o1 = x1 * cs - x2 * sn;
        float o2 = x2 * cs + x1 * sn;
        buf[base + i]      = o1;
        buf[base + 64 + i] = o2;
        local = fmaxf(fabsf(o1), fabsf(o2));
    }
    unsigned bits = __float_as_uint(local);
#pragma unroll
    for (int o = 16; o; o >>= 1) bits = max(bits, __shfl_xor_sync(0xffffffffu, bits, o));
    __shared__ unsigned sred[8];
    int wid = threadIdx.x >> 5;
    if ((threadIdx.x & 31) == 0) sred[wid] = bits;
    __syncthreads();
    if (threadIdx.x == 0) {
        unsigned m = sred[0];
#pragma unroll
        for (int w = 1; w < 8; w++) m = max(m, sred[w]);
        atomicMax(&g_amax[slot], m);
    }
}

__global__ __launch_bounds__(256) void absmax_kernel(const float* __restrict__ buf, int coloff,
                                                     int ncols, int slot)
{
    int idx = blockIdx.x * 256 + threadIdx.x;
    float local = 0.f;
    if (idx < S_LEN * ncols) {
        int s = idx / ncols, c = idx % ncols;
        local = fabsf(buf[(size_t)s * NQKV + coloff + c]);
    }
    unsigned bits = __float_as_uint(local);
#pragma unroll
    for (int o = 16; o; o >>= 1) bits = max(bits, __shfl_xor_sync(0xffffffffu, bits, o));
    __shared__ unsigned sred[8];
    int wid = threadIdx.x >> 5;
    if ((threadIdx.x & 31) == 0) sred[wid] = bits;
    __syncthreads();
    if (threadIdx.x == 0) {
        unsigned m = sred[0];
#pragma unroll
        for (int w = 1; w < 8; w++) m = max(m, sred[w]);
        atomicMax(&g_amax[slot], m);
    }
}

// ---------------- quant to integer bf16: out = bf16(rint(x/scale)), exact ----------------
__global__ __launch_bounds__(256) void quant_int_kernel(const float* __restrict__ buf, int coloff,
                                                        int ncols, __nv_bfloat16* __restrict__ out,
                                                        int slot)
{
    int idx = blockIdx.x * 256 + threadIdx.x;
    if (idx < S_LEN * ncols) {
        int s = idx / ncols, c = idx % ncols;
        float mx = __uint_as_float(g_amax[slot]);
        float sc = mx / 127.0f;
        float x  = buf[(size_t)s * NQKV + coloff + c];
        out[idx] = __float2bfloat16(rintf(x / sc));   // |i| <= 127, exact in bf16
    }
}

// ---------------- tensor-core flash attention (exact integer QK, split-bf16 PV) ----------
// BM=128, BN=64, 8 warps (warp = 16 Q rows). Q frags in regs, K/V double-buffered smem.
#define FLASH_SMEM (32768 + 2 * 32768)   // Q 32KB + 2 stages x (K 16KB + V 16KB)

__global__ __launch_bounds__(256) void flash_mma(const __nv_bfloat16* __restrict__ Qi,
                                                 const __nv_bfloat16* __restrict__ Ki,
                                                 const __nv_bfloat16* __restrict__ Vi,
                                                 __nv_bfloat16* __restrict__ Oh,
                                                 __nv_bfloat16* __restrict__ Ol)
{
    extern __shared__ char smem[];
    const uint32_t sb = smem_u32(smem);
    const int t = threadIdx.x, lane = t & 31, w = t >> 5;
    const int qt  = (int)gridDim.x - 1 - (int)blockIdx.x;   // heavy tiles first
    const int h   = blockIdx.y;
    const int kvh = h >> 2;
    const int q0  = qt * 128;
    const int wm0 = w * 16;

    const float scq = __uint_as_float(g_amax[0]) * (1.f / 127.f);
    const float sck = __uint_as_float(g_amax[1]) * (1.f / 127.f);
    const float scv = __uint_as_float(g_amax[2]) * (1.f / 127.f);
    const float sscale = scq * sck * 0.08838834764831845f;  // /sqrt(128)

    auto loadKV = [&](int jj, int st) {
        uint32_t kbase = sb + 32768 + st * 32768;
        int k0r = jj * 64;
#pragma unroll
        for (int i = 0; i < 4; i++) {
            int idx = t + i * 256;
            int r = idx >> 4, u = idx & 15;
            const __nv_bfloat16* gk = Ki + (size_t)(k0r + r) * (NKV * HD) + (size_t)kvh * HD + u * 8;
            const __nv_bfloat16* gv = Vi + (size_t)(k0r + r) * (NKV * HD) + (size_t)kvh * HD + u * 8;
            cp_async16(kbase + swz256(r, u), gk);
            cp_async16(kbase + 16384 + swz256(r, u), gv);
        }
    };

    // prologue: Q tile + KV tile 0 -> group 0
#pragma unroll
    for (int i = 0; i < 8; i++) {
        int idx = t + i * 256;
        int r = idx >> 4, u = idx & 15;
        cp_async16(sb + swz256(r, u), Qi + (size_t)(q0 + r) * (NH * HD) + (size_t)h * HD + u * 8);
    }
    loadKV(0, 0);
    cp_commit();

    uint32_t qf[8][4];
    float o[16][4];
#pragma unroll
    for (int i = 0; i < 16; i++)
#pragma unroll
        for (int e = 0; e < 4; e++) o[i][e] = 0.f;
    float m0_ = NEG_INF, m1_ = NEG_INF, l0_ = 0.f, l1_ = 0.f;

    const int ntiles = 2 * qt + 2;
    for (int j = 0; j < ntiles; j++) {
        if (j + 1 < ntiles) { loadKV(j + 1, (j + 1) & 1); cp_commit(); cp_wait1(); }
        else               { cp_wait0(); }
        __syncthreads();

        if (j == 0) {
#pragma unroll
            for (int ks = 0; ks < 8; ks++)
                ldsm_x4(qf[ks], sb + swz256(wm0 + (lane & 15), ks * 2 + (lane >> 4)));
        }

        const uint32_t kb = sb + 32768 + (j & 1) * 32768;
        const uint32_t vb = kb + 16384;

        // S = Q K^T (exact integer math in fp32 accum)
        float s[8][4];
#pragma unroll
        for (int na = 0; na < 8; na++)
#pragma unroll
            for (int e = 0; e < 4; e++) s[na][e] = 0.f;

#pragma unroll
        for (int ks = 0; ks < 8; ks++) {
            uint32_t kf[8][2];
            {
                const int br  = lane & 7;
                const int nat = lane >> 4;
                const int bcb = ks * 2 + ((lane >> 3) & 1);
#pragma unroll
                for (int p = 0; p < 4; p++) {
                    uint32_t r[4];
                    ldsm_x4(r, kb + swz256(p * 16 + nat * 8 + br, bcb));
                    kf[2 * p][0] = r[0]; kf[2 * p][1] = r[1];
                    kf[2 * p + 1][0] = r[2]; kf[2 * p + 1][1] = r[3];
                }
            }
#pragma unroll
            for (int na = 0; na < 8; na++) mma16816(s[na], qf[ks], kf[na]);
        }

        // scale + causal mask
        const bool masked = (j >= 2 * qt);
        const int gq0 = q0 + wm0 + (lane >> 2);
#pragma unroll
        for (int na = 0; na < 8; na++) {
            int gk = j * 64 + na * 8 + (lane & 3) * 2;
#pragma unroll
            for (int e = 0; e < 4; e++) {
                float val = s[na][e] * sscale;
                if (masked) {
                    int gq = gq0 + ((e >= 2) ? 8 : 0);
                    if (gk + (e & 1) > gq) val = NEG_INF;
                }
                s[na][e] = val;
            }
        }

        // online softmax (2 rows per thread, quad-shared)
        float mx0 = NEG_INF, mx1 = NEG_INF;
#pragma unroll
        for (int na = 0; na < 8; na++) {
            mx0 = fmaxf(mx0, fmaxf(s[na][0], s[na][1]));
            mx1 = fmaxf(mx1, fmaxf(s[na][2], s[na][3]));
        }
        mx0 = fmaxf(mx0, __shfl_xor_sync(0xffffffffu, mx0, 1));
        mx0 = fmaxf(mx0, __shfl_xor_sync(0xffffffffu, mx0, 2));
        mx1 = fmaxf(mx1, __shfl_xor_sync(0xffffffffu, mx1, 1));
        mx1 = fmaxf(mx1, __shfl_xor_sync(0xffffffffu, mx1, 2));
        float mn0 = fmaxf(m0_, mx0), mn1 = fmaxf(m1_, mx1);
        float a0 = __expf(m0_ - mn0), a1 = __expf(m1_ - mn1);
        float sum0 = 0.f, sum1 = 0.f;
#pragma unroll
        for (int na = 0; na < 8; na++) {
            s[na][0] = __expf(s[na][0] - mn0); sum0 += s[na][0];
            s[na][1] = __expf(s[na][1] - mn0); sum0 += s[na][1];
            s[na][2] = __expf(s[na][2] - mn1); sum1 += s[na][2];
            s[na][3] = __expf(s[na][3] - mn1); sum1 += s[na][3];
        }
        sum0 += __shfl_xor_sync(0xffffffffu, sum0, 1);
        sum0 += __shfl_xor_sync(0xffffffffu, sum0, 2);
        sum1 += __shfl_xor_sync(0xffffffffu, sum1, 1);
        sum1 += __shfl_xor_sync(0xffffffffu, sum1, 2);
        l0_ = l0_ * a0 + sum0;  m0_ = mn0;
        l1_ = l1_ * a1 + sum1;  m1_ = mn1;
#pragma unroll
        for (int na = 0; na < 16; na++) {
            o[na][0] *= a0; o[na][1] *= a0; o[na][2] *= a1; o[na][3] *= a1;
        }

        // O += P V  (split-bf16 P, exact integer V via trans-ldmatrix)
#pragma unroll
        for (int kb4 = 0; kb4 < 4; kb4++) {
            uint32_t ah[4], al2[4];
            splitpack(s[2 * kb4][0],     s[2 * kb4][1],     ah[0], al2[0]);
            splitpack(s[2 * kb4][2],     s[2 * kb4][3],     ah[1], al2[1]);
            splitpack(s[2 * kb4 + 1][0], s[2 * kb4 + 1][1], ah[2], al2[2]);
            splitpack(s[2 * kb4 + 1][2], s[2 * kb4 + 1][3], ah[3], al2[3]);
            uint32_t vf[16][2];
#pragma unroll
            for (int p = 0; p < 8; p++) {
                uint32_t r[4];
                ldsm_x4_t(r, vb + swz256(kb4 * 16 + (lane & 15), p * 2 + (lane >> 4)));
                vf[2 * p][0] = r[0]; vf[2 * p][1] = r[1];
                vf[2 * p + 1][0] = r[2]; vf[2 * p + 1][1] = r[3];
            }
#pragma unroll
            for (int na = 0; na < 16; na++) {
                mma16816(o[na], ah, vf[na]);
                mma16816(o[na], al2, vf[na]);
            }
        }
        __syncthreads();   // stage (j&1) free for prefetch in next iteration
    }

    // epilogue: normalize, scale by scv, split to bf16 hi/lo, store
    const float f0 = scv / l0_, f1 = scv / l1_;
    const int r0g = q0 + wm0 + (lane >> 2);
#pragma unroll
    for (int na = 0; na < 16; na++) {
        int col = h * HD + na * 8 + (lane & 3) * 2;
        uint32_t hw, lw;
        splitpack(o[na][0] * f0, o[na][1] * f0, hw, lw);
        *(uint32_t*)(Oh + (size_t)r0g * (NH * HD) + col) = hw;
        *(uint32_t*)(Ol + (size_t)r0g * (NH * HD) + col) = lw;
        splitpack(o[na][2] * f1, o[na][3] * f1, hw, lw);
        *(uint32_t*)(Oh + (size_t)(r0g + 8) * (NH * HD) + col) = hw;
        *(uint32_t*)(Ol + (size_t)(r0g + 8) * (NH * HD) + col) = lw;
    }
}

// ---------------- launch ----------------
extern "C" void kernel_launch(void* const* d_in, const int* in_sizes, int n_in,
                              void* d_out, int out_size)
{
    (void)in_sizes; (void)n_in; (void)out_size;
    const float* hs  = (const float*)d_in[0];
    const int*   pos = (const int*)d_in[2];
    const float* wq  = (const float*)d_in[3];
    const float* wk  = (const float*)d_in[4];
    const float* wv  = (const float*)d_in[5];
    const float* wo  = (const float*)d_in[6];
    float*       out = (float*)d_out;

    float* qkv;
    __nv_bfloat16 *qi, *ki, *vi, *hsh, *hsl, *ath, *atl, *wth, *wtl, *woh, *wol;
    cudaGetSymbolAddress((void**)&qkv, g_qkv);
    cudaGetSymbolAddress((void**)&qi,  g_qi);
    cudaGetSymbolAddress((void**)&ki,  g_ki);
    cudaGetSymbolAddress((void**)&vi,  g_vi);
    cudaGetSymbolAddress((void**)&hsh, g_hs_h);
    cudaGetSymbolAddress((void**)&hsl, g_hs_l);
    cudaGetSymbolAddress((void**)&ath, g_at_h);
    cudaGetSymbolAddress((void**)&atl, g_at_l);
    cudaGetSymbolAddress((void**)&wth, g_wt_h);
    cudaGetSymbolAddress((void**)&wtl, g_wt_l);
    cudaGetSymbolAddress((void**)&woh, g_wot_h);
    cudaGetSymbolAddress((void**)&wol, g_wot_l);

    cudaFuncSetAttribute(mm_bf16<1>, cudaFuncAttributeMaxDynamicSharedMemorySize, MM_SMEM);
    cudaFuncSetAttribute(mm_bf16<0>, cudaFuncAttributeMaxDynamicSharedMemorySize, MM_SMEM);
    cudaFuncSetAttribute(flash_mma, cudaFuncAttributeMaxDynamicSharedMemorySize, FLASH_SMEM);

    reset_amax_kernel<<<1, 32>>>();

    // preprocess: split activations, transpose+split weights (QKV fused into one [6144,K])
    split_kernel<<<(S_LEN * HID) / 256, 256>>>(hs, hsh, hsl, S_LEN * HID);
    transpose_split_kernel<<<dim3((NH * HD) / 32, HID / 32), 256>>>(wq, wth, wtl, HID, NH * HD, 0);
    transpose_split_kernel<<<dim3((NKV * HD) / 32, HID / 32), 256>>>(wk, wth, wtl, HID, NKV * HD, 4096);
    transpose_split_kernel<<<dim3((NKV * HD) / 32, HID / 32), 256>>>(wv, wth, wtl, HID, NKV * HD, 5120);
    transpose_split_kernel<<<dim3(HID / 32, HID / 32), 256>>>(wo, woh, wol, NH * HD, HID, 0);

    // fused QKV projection (4-term split for quant safety)
    mm_bf16<1><<<dim3(NQKV / 128, S_LEN / 128), 256, MM_SMEM>>>(hsh, hsl, wth, wtl, qkv,
                                                                S_LEN, NQKV, HID);

    // rope + absmax + integer quant
    rope_absmax_kernel<<<(S_LEN * NH * 64) / 256, 256>>>(qkv, 0, NH, pos, 0);
    rope_absmax_kernel<<<(S_LEN * NKV * 64) / 256, 256>>>(qkv, 4096, NKV, pos, 1);
    absmax_kernel<<<(S_LEN * NKV * HD) / 256, 256>>>(qkv, 5120, NKV * HD, 2);
    quant_int_kernel<<<(S_LEN * NH * HD) / 256, 256>>>(qkv, 0, NH * HD, qi, 0);
    quant_int_kernel<<<(S_LEN * NKV * HD) / 256, 256>>>(qkv, 4096, NKV * HD, ki, 1);
    quant_int_kernel<<<(S_LEN * NKV * HD) / 256, 256>>>(qkv, 5120, NKV * HD, vi, 2);

    // tensor-core flash attention (writes attn splits directly)
    flash_mma<<<dim3(S_LEN / 128, NH), 256, FLASH_SMEM>>>(qi, ki, vi, ath, atl);

    // output projection (3-term split)
    mm_bf16<0><<<dim3(HID / 128, S_LEN / 128), 256, MM_SMEM>>>(ath, atl, woh, wol, out,
                                                               S_LEN, HID, HID);
}